// round 17
// baseline (speedup 1.0000x reference)
#include <cuda_runtime.h>
#include <cuda_fp16.h>
#include <cstdint>
#include <math.h>

#define B_DIM 16
#define SQ    2048
#define SKV   2048
#define D_DIM 256
#define BQ    64
#define BK    64
#define NIT   (SKV / BK)
#define KC    (0.022097086912079608f * 1.4426950408889634f)  // (1/sqrt(2048)) * log2(e)

#define NTHR  128

#define LDS   264          // sQ/sY row stride (fp16 elems), 528B
#define LDSB  528
#define LDP   72           // sP row stride (fp16 elems), 144B
#define LDPB  144

// smem layout (bytes) — sized so TWO CTAs fit per SM (2x111104 = 222208 <= 228KB)
#define OFF_Q 0
#define SZ_Q  (BQ * LDSB)                // 33792
#define OFF_Y (OFF_Q + SZ_Q)
#define SZ_Y  (BK * LDSB)                // 33792 per buffer (x2)
#define OFF_P (OFF_Y + 2 * SZ_Y)         // 101376
#define SZ_P  (BQ * LDPB)                // 9216 (single buffer)
#define OFF_L (OFF_P + SZ_P)             // 110592
#define SMEM_BYTES (OFF_L + 2 * BQ * 4)  // 111104

__device__ __half g_yh[(size_t)B_DIM * SKV * D_DIM];

__device__ __forceinline__ uint32_t sptr(const void* p) {
    return (uint32_t)__cvta_generic_to_shared(p);
}

__device__ __forceinline__ void ldsm4(uint32_t* r, uint32_t a) {
    asm("ldmatrix.sync.aligned.m8n8.x4.shared.b16 {%0,%1,%2,%3}, [%4];"
        : "=r"(r[0]), "=r"(r[1]), "=r"(r[2]), "=r"(r[3]) : "r"(a) : "memory");
}
__device__ __forceinline__ void ldsm4t(uint32_t* r, uint32_t a) {
    asm("ldmatrix.sync.aligned.m8n8.x4.trans.shared.b16 {%0,%1,%2,%3}, [%4];"
        : "=r"(r[0]), "=r"(r[1]), "=r"(r[2]), "=r"(r[3]) : "r"(a) : "memory");
}
__device__ __forceinline__ void mma_f32(float* c, const uint32_t* a, uint32_t b0, uint32_t b1) {
    asm("mma.sync.aligned.m16n8k16.row.col.f32.f16.f16.f32 "
        "{%0,%1,%2,%3}, {%4,%5,%6,%7}, {%8,%9}, {%0,%1,%2,%3};"
        : "+f"(c[0]), "+f"(c[1]), "+f"(c[2]), "+f"(c[3])
        : "r"(a[0]), "r"(a[1]), "r"(a[2]), "r"(a[3]), "r"(b0), "r"(b1));
}
// packed fp16 exp2 (ex2.approx.f16x2, sm_75+)
__device__ __forceinline__ __half2 h2ex2(__half2 v) {
    uint32_t r, a = *reinterpret_cast<uint32_t*>(&v);
    asm("ex2.approx.f16x2 %0, %1;" : "=r"(r) : "r"(a));
    return *reinterpret_cast<__half2*>(&r);
}
__device__ __forceinline__ void cpasync16(uint32_t dst, const void* src) {
    asm volatile("cp.async.cg.shared.global [%0], [%1], 16;" :: "r"(dst), "l"(src) : "memory");
}
#define CP_COMMIT() asm volatile("cp.async.commit_group;" ::: "memory")
#define CP_WAIT0()  asm volatile("cp.async.wait_group 0;" ::: "memory")

// -------- pre-convert fp32 -> fp16 for y only (x handled in fa prologue) ----
// 8 independent float4 loads per thread for high MLP (DRAM-bandwidth shaped).
__global__ void __launch_bounds__(256) convert_y(const float* __restrict__ y) {
    size_t base = ((size_t)blockIdx.x * 256 + threadIdx.x) * 4;
    const size_t stride = (size_t)gridDim.x * 256 * 4;
#pragma unroll
    for (int j = 0; j < 8; j++) {
        size_t i = base + (size_t)j * stride;
        float4 f = *reinterpret_cast<const float4*>(y + i);
        __half2 h0 = __floats2half2_rn(f.x, f.y);
        __half2 h1 = __floats2half2_rn(f.z, f.w);
        uint2 u;
        u.x = *reinterpret_cast<uint32_t*>(&h0);
        u.y = *reinterpret_cast<uint32_t*>(&h1);
        *reinterpret_cast<uint2*>(g_yh + i) = u;
    }
}

extern __shared__ char smem_raw[];

__global__ void __launch_bounds__(NTHR, 2)
fa_kernel(const float* __restrict__ x, const float* __restrict__ mask,
          float* __restrict__ out) {
    const int tid  = threadIdx.x;
    const int lane = tid & 31;
    const int warp = tid >> 5;          // 0..3
    // phase A roles: 2 q-groups x 2 kv-halves, warp tile 32x32
    const int wq = warp >> 1;
    const int ws = warp & 1;
    // phase B roles: all 4 warps share q 0..63; each owns 64 of d=256
    const int wd = warp;

    const int b  = blockIdx.y;
    const int q0 = blockIdx.x * BQ;

    const uint32_t sm = sptr(smem_raw);
    float* sL = reinterpret_cast<float*>(smem_raw + OFF_L);

    // ---- prologue ----
    // Y tile 0 via cp.async (fp16 source); Q from fp32 x, converted inline
    // WITH the softmax constant KC folded in (S then = logit pre-mask).
    const float* xg32 = x + ((size_t)b * SQ + q0) * D_DIM;
    const __half* yg  = g_yh + (size_t)b * SKV * D_DIM;
#pragma unroll
    for (int i = 0; i < 16; i++) {
        int unit = tid + (i << 7);
        int r = unit >> 5, u = unit & 31;
        cpasync16(sm + OFF_Y + r * LDSB + u * 16, yg + (size_t)r * D_DIM + u * 8);
    }
    CP_COMMIT();
#pragma unroll
    for (int i = 0; i < 16; i++) {
        int unit = tid + (i << 7);      // 2048 units of 16B-fp16 (32 per row)
        int r = unit >> 5, u = unit & 31;
        const float* src = xg32 + (size_t)r * D_DIM + u * 8;
        float4 f0 = reinterpret_cast<const float4*>(src)[0];
        float4 f1 = reinterpret_cast<const float4*>(src)[1];
        __half2 h0 = __floats2half2_rn(f0.x * KC, f0.y * KC);
        __half2 h1 = __floats2half2_rn(f0.z * KC, f0.w * KC);
        __half2 h2 = __floats2half2_rn(f1.x * KC, f1.y * KC);
        __half2 h3 = __floats2half2_rn(f1.z * KC, f1.w * KC);
        uint4 v;
        v.x = *reinterpret_cast<uint32_t*>(&h0);
        v.y = *reinterpret_cast<uint32_t*>(&h1);
        v.z = *reinterpret_cast<uint32_t*>(&h2);
        v.w = *reinterpret_cast<uint32_t*>(&h3);
        *reinterpret_cast<uint4*>(smem_raw + OFF_Q + r * LDSB + u * 16) = v;
    }
    CP_WAIT0();
    __syncthreads();

    // ---- precomputed addresses ----
    const int jb = lane >> 3;
    // phase A: A frags from sQ (rows wq*32.., two 16-row halves)
    const uint32_t aX0 = sm + OFF_Q + (uint32_t)(((wq * 32 + (lane & 15)) * LDS + ((lane >> 4) << 3)) << 1);
    const uint32_t aX1 = aX0 + 16 * LDSB;
    // phase A: B frags from sY (kv rows ws*32..), k = d, non-trans
    const int bRow = (lane & 7) + ((jb >> 1) << 3);
    const int bCol = (jb & 1) << 3;
    const uint32_t bS0 = sm + OFF_Y + (uint32_t)(((ws * 32 + bRow) * LDS + bCol) << 1);
    // phase B: A frags from sP (rows 0..63)
    const uint32_t aP = sm + OFF_P + (uint32_t)((((lane & 15)) * LDP + ((lane >> 4) << 3)) << 1);
    // phase B: B frags from sY, k = kv, n = d -> trans
    const int vRow = (lane & 7) + ((jb & 1) << 3);
    const int vCol = ((jb >> 1) << 3) + wd * 64;
    const uint32_t bV = sm + OFF_Y + (uint32_t)(((vRow * LDS) + vCol) << 1);
    // P store base (phase A role)
    const uint32_t pSt = sm + OFF_P + (uint32_t)(((wq * 32 + (lane >> 2)) * LDP + ws * 32 + ((lane & 3) << 1)) << 1);
    // mask base (phase A role)
    const float* mBase = mask + ((size_t)(b * SQ + q0 + wq * 32 + (lane >> 2))) * SKV
                              + ws * 32 + ((lane & 3) << 1);

    float o[4][8][4];
#pragma unroll
    for (int mi = 0; mi < 4; mi++)
#pragma unroll
        for (int ni = 0; ni < 8; ni++) {
            o[mi][ni][0] = 0.f; o[mi][ni][1] = 0.f; o[mi][ni][2] = 0.f; o[mi][ni][3] = 0.f;
        }
    float lsum[4] = {0.f, 0.f, 0.f, 0.f};

    for (int it = 0; it < NIT; it++) {
        const uint32_t yoffC = (uint32_t)(it & 1) * SZ_Y;

        // (1) prefetch next Y tile into the other buffer
        if (it + 1 < NIT) {
            const __half* ysrc = yg + (size_t)(it + 1) * BK * D_DIM;
            const uint32_t ydst = sm + OFF_Y + (uint32_t)((it & 1) ^ 1) * SZ_Y;
#pragma unroll
            for (int i = 0; i < 16; i++) {
                int unit = tid + (i << 7);
                int r = unit >> 5, u = unit & 31;
                cpasync16(ydst + r * LDSB + u * 16, ysrc + (size_t)r * D_DIM + u * 8);
            }
            CP_COMMIT();
        }

        // (2) mask values for this tile (early issue, high MLP)
        float2 mv[2][2][4];
#pragma unroll
        for (int mi = 0; mi < 2; mi++)
#pragma unroll
            for (int hi = 0; hi < 2; hi++)
#pragma unroll
                for (int ni = 0; ni < 4; ni++)
                    mv[mi][hi][ni] = *reinterpret_cast<const float2*>(
                        mBase + (size_t)(mi * 16 + hi * 8) * SKV + (size_t)it * BK + ni * 8);

        // (3) phase A: S = (Q*KC) @ K^T on Y[cur], warp tile 32x32, f32 accum
        float c[2][4][4];
#pragma unroll
        for (int mi = 0; mi < 2; mi++)
#pragma unroll
            for (int ni = 0; ni < 4; ni++) {
                c[mi][ni][0] = 0.f; c[mi][ni][1] = 0.f; c[mi][ni][2] = 0.f; c[mi][ni][3] = 0.f;
            }
#pragma unroll
        for (int ks = 0; ks < 16; ks++) {
            uint32_t a0[4], a1[4], b0[4], b1[4];
            ldsm4(a0, aX0 + (ks << 5));
            ldsm4(a1, aX1 + (ks << 5));
            ldsm4(b0, bS0 + yoffC + (ks << 5));
            ldsm4(b1, bS0 + yoffC + 16 * LDSB + (ks << 5));
            mma_f32(c[0][0], a0, b0[0], b0[1]);
            mma_f32(c[0][1], a0, b0[2], b0[3]);
            mma_f32(c[0][2], a0, b1[0], b1[1]);
            mma_f32(c[0][3], a0, b1[2], b1[3]);
            mma_f32(c[1][0], a1, b0[0], b0[1]);
            mma_f32(c[1][1], a1, b0[2], b0[3]);
            mma_f32(c[1][2], a1, b1[0], b1[1]);
            mma_f32(c[1][3], a1, b1[2], b1[3]);
        }

        // (4) softmax, packed-fp16: KC already folded into Q, so
        //     logit pair = cvt_f16x2(c) * cvt_f16x2(mask); p = ex2.f16x2.
#pragma unroll
        for (int mi = 0; mi < 2; mi++)
#pragma unroll
            for (int hi = 0; hi < 2; hi++) {
                __half2 hacc = __floats2half2_rn(0.f, 0.f);
#pragma unroll
                for (int ni = 0; ni < 4; ni++) {
                    __half2 mh = __floats2half2_rn(mv[mi][hi][ni].x,
                                                   mv[mi][hi][ni].y);
                    __half2 ch = __floats2half2_rn(c[mi][ni][hi * 2 + 0],
                                                   c[mi][ni][hi * 2 + 1]);
                    __half2 p  = h2ex2(__hmul2(ch, mh));
                    *reinterpret_cast<__half2*>(
                        smem_raw + (pSt - sm) + (mi * 16 + hi * 8) * LDPB + ni * 16) = p;
                    hacc = __hadd2(hacc, p);
                }
                float2 fa2 = __half22float2(hacc);
                lsum[mi * 2 + hi] += fa2.x + fa2.y;
            }
        __syncthreads();   // P visible (Y[cur] still in use; prefetch hits other buf)

        // (5) phase B: O += P @ Y[cur], warp tile 64x64
#pragma unroll
        for (int ks = 0; ks < 4; ks++) {
            uint32_t a[4][4];
#pragma unroll
            for (int mi = 0; mi < 4; mi++)
                ldsm4(a[mi], aP + mi * 16 * LDPB + (ks << 5));
#pragma unroll
            for (int t2 = 0; t2 < 4; t2++) {
                uint32_t bb[4];
                ldsm4t(bb, bV + yoffC + ks * 16 * LDSB + (t2 << 5));
#pragma unroll
                for (int mi = 0; mi < 4; mi++) {
                    mma_f32(o[mi][2 * t2],     a[mi], bb[0], bb[1]);
                    mma_f32(o[mi][2 * t2 + 1], a[mi], bb[2], bb[3]);
                }
            }
        }

        // (6) Y[next] landed; P free; Y[cur] free after this point
        if (it + 1 < NIT) CP_WAIT0();
        __syncthreads();
    }

    // ---------- epilogue: reduce l, write out = O/l + x ----------
#pragma unroll
    for (int s = 0; s < 4; s++) {
        float v = lsum[s];
        v += __shfl_xor_sync(0xffffffffu, v, 1);
        v += __shfl_xor_sync(0xffffffffu, v, 2);
        if ((lane & 3) == 0)
            sL[ws * BQ + wq * 32 + (s >> 1) * 16 + (s & 1) * 8 + (lane >> 2)] = v;
    }
    __syncthreads();

#pragma unroll
    for (int mi = 0; mi < 4; mi++)
#pragma unroll
        for (int hi = 0; hi < 2; hi++) {
            const int r = mi * 16 + hi * 8 + (lane >> 2);
            const float inv = 1.f / (sL[r] + sL[BQ + r]);
            const size_t gr = (size_t)b * SQ + q0 + r;
            const float* xr = x + gr * D_DIM + wd * 64 + ((lane & 3) << 1);
            float* og = out + gr * D_DIM + wd * 64 + ((lane & 3) << 1);
#pragma unroll
            for (int ni = 0; ni < 8; ni++) {
                float2 xv = *reinterpret_cast<const float2*>(xr + ni * 8);
                float2 w;
                w.x = o[mi][ni][hi * 2 + 0] * inv + xv.x;
                w.y = o[mi][ni][hi * 2 + 1] * inv + xv.y;
                *reinterpret_cast<float2*>(og + ni * 8) = w;
            }
        }
}

extern "C" void kernel_launch(void* const* d_in, const int* in_sizes, int n_in,
                              void* d_out, int out_size) {
    const float* x    = (const float*)d_in[0];
    const float* y    = (const float*)d_in[1];
    const float* mask = (const float*)d_in[2];
    float* out        = (float*)d_out;

    // y fp32 -> fp16 (x is converted inside fa_kernel's prologue)
    convert_y<<<(B_DIM * SKV * D_DIM) / (256 * 32), 256>>>(y);

    cudaFuncSetAttribute(fa_kernel, cudaFuncAttributeMaxDynamicSharedMemorySize, SMEM_BYTES);
    dim3 grid(SQ / BQ, B_DIM);
    fa_kernel<<<grid, NTHR, SMEM_BYTES>>>(x, mask, out);
}